// round 6
// baseline (speedup 1.0000x reference)
#include <cuda_runtime.h>

// CRF loss, linear-domain scan, split-dot version.
// One 256-thread CTA per batch row (grid=256, 2 CTAs/SM -> 4 warps/SMSP).
// Thread j<128: column j, summation half i in [0,64) + final combine.
// Thread j>=128: column j-128, half i in [64,128); its partial goes via smem.
// Upper threads do all group bookkeeping (emission LDG/exp into eBuf) in the
// otherwise-idle phase B. Deferred power-of-2 renorm every 4 steps.

namespace {
constexpr int TT = 128;
constexpr int SS = 1024;
constexpr int NB = 256;
constexpr int START_TAG = 126;
constexpr int END_TAG = 127;
}

typedef unsigned long long ull;
__device__ double g_part[NB];
__device__ unsigned int g_ticket;

__device__ __forceinline__ ull pack2f(float lo, float hi) {
    ull r;
    asm("mov.b64 %0, {%1, %2};" : "=l"(r) : "f"(lo), "f"(hi));
    return r;
}

// half dot: 64 alphas (16 double2 broadcasts) x 32 f32x2 fma, 4 accumulators
__device__ __forceinline__ float dothalf(const float* __restrict__ arh,
                                         const ull* __restrict__ E) {
    ull acc[4] = {0ull, 0ull, 0ull, 0ull};
    const double2* ap = reinterpret_cast<const double2*>(arh);
#pragma unroll
    for (int k = 0; k < 16; k++) {
        double2 d = ap[k];
        ull lo = __double_as_longlong(d.x);
        ull hi = __double_as_longlong(d.y);
        if (k & 1) {
            asm("fma.rn.f32x2 %0, %1, %2, %0;" : "+l"(acc[2]) : "l"(lo), "l"(E[2 * k]));
            asm("fma.rn.f32x2 %0, %1, %2, %0;" : "+l"(acc[3]) : "l"(hi), "l"(E[2 * k + 1]));
        } else {
            asm("fma.rn.f32x2 %0, %1, %2, %0;" : "+l"(acc[0]) : "l"(lo), "l"(E[2 * k]));
            asm("fma.rn.f32x2 %0, %1, %2, %0;" : "+l"(acc[1]) : "l"(hi), "l"(E[2 * k + 1]));
        }
    }
    asm("add.rn.f32x2 %0, %0, %1;" : "+l"(acc[0]) : "l"(acc[2]));
    asm("add.rn.f32x2 %0, %0, %1;" : "+l"(acc[1]) : "l"(acc[3]));
    asm("add.rn.f32x2 %0, %0, %1;" : "+l"(acc[0]) : "l"(acc[1]));
    float lo, hi;
    asm("mov.b64 {%0, %1}, %2;" : "=f"(lo), "=f"(hi) : "l"(acc[0]));
    return lo + hi;
}

__global__ void __launch_bounds__(256, 2)
crf_scan_kernel(const float* __restrict__ em, const int* __restrict__ tags,
                const float* __restrict__ trans, float* __restrict__ out) {
    const int b = blockIdx.x;
    const int j = threadIdx.x;
    const bool lower = (j < 128);
    const int c = j & 127;
    const int base = lower ? 0 : 64;

    __shared__ __align__(16) float alpha[2][TT];
    __shared__ __align__(16) float ppart[TT];
    __shared__ __align__(16) float eBuf[2][4][TT];
    __shared__ __align__(16) float red[4];
    __shared__ __align__(16) float scratch[16];
    __shared__ int s_last;

    const float* emb = em + (size_t)b * SS * TT;
    const int* tg = tags + b * SS;

    // half E column: pairs (base+2m, base+2m+1) for column c
    ull E[32];
#pragma unroll
    for (int m = 0; m < 32; m++) {
        float e0 = __expf(trans[(base + 2 * m) * TT + c]);
        float e1 = __expf(trans[(base + 2 * m + 1) * TT + c]);
        E[m] = pack2f(e0, e1);
    }

    // ---- gold path score over all 256 threads ----
    float gold = 0.f;
#pragma unroll
    for (int r = 0; r < 4; r++) {
        int s = r * 256 + j;
        int cur = tg[s];
        int prev = (s == 0) ? START_TAG : tg[s - 1];
        gold += emb[s * TT + cur] + trans[prev * TT + cur];
    }
    if (j == 0) gold += trans[tg[SS - 1] * TT + END_TAG];

    // one-time: max of END transition row (lower threads)
    float tE = lower ? trans[END_TAG * TT + c] : -1e30f;
    {
        float m = tE;
#pragma unroll
        for (int o = 16; o > 0; o >>= 1)
            m = fmaxf(m, __shfl_xor_sync(0xffffffffu, m, o));
        if (lower && (j & 31) == 0) scratch[j >> 5] = m;
    }
    if (lower) alpha[0][c] = (c == START_TAG) ? 1.f : 0.f;
    if (j < 4) red[j] = 1.0f;  // first group: ex = 0, sc = 1
    if (!lower) {
#pragma unroll
        for (int q = 0; q < 4; q++)
            eBuf[0][q][c] = __expf(emb[(1 + q) * TT + c]);
    }
    __syncthreads();
    const float mTE = fmaxf(fmaxf(scratch[0], scratch[1]),
                            fmaxf(scratch[2], scratch[3]));

    // ---- scan, t = 1..1023, groups of 4 ----
    int le = 0;
    int cur = 0;
    float gA = 0.f, gB = 0.f, gC = 0.f, gD = 0.f;

#pragma unroll 1
    for (int g = 0; g < 255; g++) {
        const int buf = g & 1, nbuf = buf ^ 1;
        float sc = 1.f;
        // ===== step 0 (consume renorm scale) =====
        float e = 0.f;
        if (lower) {
            float4 r4 = *reinterpret_cast<const float4*>(red);
            float mm = fmaxf(fmaxf(r4.x, r4.y), fmaxf(r4.z, r4.w));
            int ex = (__float_as_int(mm) >> 23) - 127;
            le += ex;
            sc = __int_as_float((127 - ex) << 23);
            e = eBuf[buf][0][c] * sc;
        }
        float p = dothalf(&alpha[cur][base], E);
        if (!lower) ppart[c] = p;
        __syncthreads();
        if (lower) {
            alpha[cur ^ 1][c] = (p + ppart[c]) * e;
        } else {
            const int tn = 4 * g + 5;
            gA = emb[(tn + 0) * TT + c];
            gB = emb[(tn + 1) * TT + c];
            gC = emb[(tn + 2) * TT + c];
            gD = (tn + 3 <= 1023) ? emb[(tn + 3) * TT + c] : 0.f;
        }
        __syncthreads();
        cur ^= 1;
        // ===== step 1 =====
        if (lower) e = eBuf[buf][1][c];
        p = dothalf(&alpha[cur][base], E);
        if (!lower) ppart[c] = p;
        __syncthreads();
        if (lower) {
            alpha[cur ^ 1][c] = (p + ppart[c]) * e;
        } else {
            eBuf[nbuf][0][c] = __expf(gA);
            eBuf[nbuf][1][c] = __expf(gB);
            eBuf[nbuf][2][c] = __expf(gC);
            eBuf[nbuf][3][c] = __expf(gD);
        }
        __syncthreads();
        cur ^= 1;
        // ===== step 2 =====
        if (lower) e = eBuf[buf][2][c];
        p = dothalf(&alpha[cur][base], E);
        if (!lower) ppart[c] = p;
        __syncthreads();
        if (lower) alpha[cur ^ 1][c] = (p + ppart[c]) * e;
        __syncthreads();
        cur ^= 1;
        // ===== step 3 (renorm) =====
        if (lower) e = eBuf[buf][3][c];
        p = dothalf(&alpha[cur][base], E);
        if (!lower) ppart[c] = p;
        __syncthreads();
        if (lower) {
            float v = (p + ppart[c]) * e;
            alpha[cur ^ 1][c] = v;
            int m;  // v >= 0: fp max == s32 max on bit patterns
            asm volatile("redux.sync.max.s32 %0, %1, 0xffffffff;"
                         : "=r"(m) : "r"(__float_as_int(v)));
            if ((j & 31) == 0) red[j >> 5] = __int_as_float(m);
        }
        __syncthreads();
        cur ^= 1;
    }
    // ---- tail: t = 1021..1023, buf = 1 ----
    {
        float sc = 1.f;
#pragma unroll
        for (int st = 0; st < 3; st++) {
            float e = 0.f;
            if (lower) {
                if (st == 0) {
                    float4 r4 = *reinterpret_cast<const float4*>(red);
                    float mm = fmaxf(fmaxf(r4.x, r4.y), fmaxf(r4.z, r4.w));
                    int ex = (__float_as_int(mm) >> 23) - 127;
                    le += ex;
                    sc = __int_as_float((127 - ex) << 23);
                    e = eBuf[1][0][c] * sc;
                } else {
                    e = eBuf[1][st][c];
                }
            }
            float p = dothalf(&alpha[cur][base], E);
            if (!lower) ppart[c] = p;
            __syncthreads();
            if (lower) alpha[cur ^ 1][c] = (p + ppart[c]) * e;
            __syncthreads();
            cur ^= 1;
        }
    }

    // ---- partition & gold reduction ----
    float x = lower ? alpha[cur][c] * __expf(tE - mTE) : 0.f;
    float y = gold;
#pragma unroll
    for (int o = 16; o > 0; o >>= 1) {
        x += __shfl_xor_sync(0xffffffffu, x, o);
        y += __shfl_xor_sync(0xffffffffu, y, o);
    }
    if ((j & 31) == 0) {
        int w = j >> 5;
        if (w < 4) scratch[w] = x;
        scratch[8 + w] = y;
    }
    __syncthreads();
    if (j == 0) {
        float sumv = scratch[0] + scratch[1] + scratch[2] + scratch[3];
        float sumg = scratch[8] + scratch[9] + scratch[10] + scratch[11] +
                     scratch[12] + scratch[13] + scratch[14] + scratch[15];
        double part = (double)le * 0.6931471805599453 + (double)mTE + log((double)sumv);
        g_part[b] = part - (double)sumg;
        __threadfence();
        unsigned int t = atomicAdd(&g_ticket, 1u);
        s_last = (t == NB - 1) ? 1 : 0;
    }
    __syncthreads();

    // ---- last CTA reduces the 256 partials and writes the mean ----
    if (s_last) {
        double d = __ldcg(&g_part[j]);
#pragma unroll
        for (int o = 16; o > 0; o >>= 1)
            d += __shfl_xor_sync(0xffffffffu, d, o);
        __shared__ double sd[8];
        if ((j & 31) == 0) sd[j >> 5] = d;
        __syncthreads();
        if (j == 0) {
            double tot = 0.0;
#pragma unroll
            for (int w = 0; w < 8; w++) tot += sd[w];
            out[0] = (float)(tot * (1.0 / NB));
            g_ticket = 0;  // reset for graph replay
        }
    }
}

extern "C" void kernel_launch(void* const* d_in, const int* in_sizes, int n_in,
                              void* d_out, int out_size) {
    const float* em = (const float*)d_in[0];     // [256,1024,128] f32
    const int* tags = (const int*)d_in[1];       // [256,1024] i32
    const float* trans = (const float*)d_in[2];  // [128,128] f32
    crf_scan_kernel<<<NB, 256>>>(em, tags, trans, (float*)d_out);
}